// round 7
// baseline (speedup 1.0000x reference)
#include <cuda_runtime.h>
#include <cuda_fp16.h>
#include <cstdint>

#define N_NODES 50000
#define N_EDGES 800000
#define TOTAL_EDGES (N_EDGES + N_NODES)   // + self loops
#define HC  512                           // HEADS * OUT_CH
#define HC2 256                           // half2s per node row
#define ROW4 64                           // uint4s (8 ch fp16) per node row

// ---- scratch (device globals: allocation-free) ----
__device__ uint4 g_xlh[N_NODES * ROW4];   // 51.2 MB, x_l rows fp16
__device__ uint4 g_xrh[N_NODES * ROW4];   // 51.2 MB, x_r rows fp16
__device__ int   g_count[N_NODES];
__device__ int   g_off[N_NODES + 1];
__device__ int   g_cur[N_NODES];
__device__ int   g_csr[TOTAL_EDGES];      // src per dst-grouped slot
__device__ int   g_src[N_EDGES];
__device__ int   g_dst[N_EDGES];
__device__ int   g_not64;                 // 1 if edge_index is int32, 0 if int64

// ---------------------------------------------------------------------------
__global__ void k_zero() {
    int i = blockIdx.x * blockDim.x + threadIdx.x;
    if (i < N_NODES) g_count[i] = 0;
    if (i == 0) g_not64 = 0;
}

// Probe dtype of edge_index. Reads only the first N_EDGES int64 words (6.4 MB),
// in-bounds under either dtype. True int64 values are all in [0, N_NODES);
// misread int32 pairs have nonzero high words almost surely -> flag.
__global__ void k_detect(const long long* __restrict__ ei64) {
    int e = blockIdx.x * blockDim.x + threadIdx.x;
    if (e < N_EDGES) {
        long long v = ei64[e];
        if (v < 0 || v >= N_NODES) g_not64 = 1;   // benign race, all write 1
    }
}

// Convert to int32 src/dst AND build the degree histogram in one pass.
__global__ void k_convert_count(const void* __restrict__ ei_raw) {
    int e = blockIdx.x * blockDim.x + threadIdx.x;
    if (e >= N_EDGES) return;
    int s, d;
    if (g_not64) {
        const int* ei32 = (const int*)ei_raw;
        s = ei32[e];
        d = ei32[N_EDGES + e];
    } else {
        const long long* ei64 = (const long long*)ei_raw;
        s = (int)ei64[e];
        d = (int)ei64[N_EDGES + e];
    }
    g_src[e] = s;
    g_dst[e] = d;
    atomicAdd(&g_count[d], 1);
}

// ---------------------------------------------------------------------------
// x_l = X @ W_l, x_r = X @ W_r, both stored fp16.
// Register-resident W: 256 threads/block, thread c owns channels {2c, 2c+1}.
// Packed fma.rn.f32x2 halves FMA issue count; X staged via smem.
#define NODES_PER_BLOCK 64
#define XBATCH 32

__global__ void __launch_bounds__(256) k_transform(const float* __restrict__ X,
                                                   const float* __restrict__ Wl,
                                                   const float* __restrict__ Wr) {
    int c   = threadIdx.x;                 // channel pair 0..255
    int nb0 = blockIdx.x * NODES_PER_BLOCK;

    unsigned long long wl[16], wr[16];
    const unsigned long long* wl2 = (const unsigned long long*)Wl;  // [16][256] f32x2
    const unsigned long long* wr2 = (const unsigned long long*)Wr;
#pragma unroll
    for (int k = 0; k < 16; k++) {
        wl[k] = wl2[k * HC2 + c];
        wr[k] = wr2[k * HC2 + c];
    }

    __shared__ float xs[XBATCH][16];
    __half2* xlh = (__half2*)g_xlh;
    __half2* xrh = (__half2*)g_xrh;

    for (int base = nb0; base < nb0 + NODES_PER_BLOCK; base += XBATCH) {
        __syncthreads();
        {
            int i0 = c;                    // 2 X elements per thread
            int n0 = base + (i0 >> 4);
            if (n0 < N_NODES) xs[i0 >> 4][i0 & 15] = X[n0 * 16 + (i0 & 15)];
            int i1 = c + 256;
            int n1 = base + (i1 >> 4);
            if (n1 < N_NODES) xs[i1 >> 4][i1 & 15] = X[n1 * 16 + (i1 & 15)];
        }
        __syncthreads();

        for (int i = 0; i < XBATCH; i++) {
            int node = base + i;
            if (node >= N_NODES) break;
            unsigned long long al, ar;
            {
                float xv = xs[i][0];
                unsigned long long xp;
                asm("mov.b64 %0, {%1, %1};" : "=l"(xp) : "f"(xv));
                asm("mul.rn.f32x2 %0, %1, %2;" : "=l"(al) : "l"(xp), "l"(wl[0]));
                asm("mul.rn.f32x2 %0, %1, %2;" : "=l"(ar) : "l"(xp), "l"(wr[0]));
            }
#pragma unroll
            for (int k = 1; k < 16; k++) {
                float xv = xs[i][k];
                unsigned long long xp;
                asm("mov.b64 %0, {%1, %1};" : "=l"(xp) : "f"(xv));
                asm("fma.rn.f32x2 %0, %1, %2, %3;" : "=l"(al) : "l"(xp), "l"(wl[k]), "l"(al));
                asm("fma.rn.f32x2 %0, %1, %2, %3;" : "=l"(ar) : "l"(xp), "l"(wr[k]), "l"(ar));
            }
            float llo, lhi, rlo, rhi;
            asm("mov.b64 {%0, %1}, %2;" : "=f"(llo), "=f"(lhi) : "l"(al));
            asm("mov.b64 {%0, %1}, %2;" : "=f"(rlo), "=f"(rhi) : "l"(ar));
            xlh[(size_t)node * HC2 + c] = __floats2half2_rn(llo, lhi);
            xrh[(size_t)node * HC2 + c] = __floats2half2_rn(rlo, rhi);
        }
    }
}

// Single-block exclusive scan over per-node degrees (+1 for self loop).
__global__ void k_scan() {
    __shared__ int sm[1024];
    int t = threadIdx.x;
    const int IT = (N_NODES + 1023) / 1024;   // 49
    int beg = t * IT;
    int end = beg + IT; if (end > N_NODES) end = N_NODES;
    int s = 0;
    for (int i = beg; i < end; i++) s += g_count[i] + 1;
    sm[t] = s;
    __syncthreads();
    for (int off = 1; off < 1024; off <<= 1) {
        int v = 0;
        if (t >= off) v = sm[t - off];
        __syncthreads();
        sm[t] += v;
        __syncthreads();
    }
    int run = sm[t] - s;                      // exclusive prefix for this chunk
    for (int i = beg; i < end; i++) {
        g_off[i] = run;
        g_cur[i] = run;
        run += g_count[i] + 1;
    }
    if (t == 1023) g_off[N_NODES] = sm[1023];
}

__global__ void k_scatter() {
    int e = blockIdx.x * blockDim.x + threadIdx.x;
    if (e < N_EDGES) {
        int p = atomicAdd(&g_cur[g_dst[e]], 1);
        g_csr[p] = g_src[e];
    } else if (e < TOTAL_EDGES) {
        int n = e - N_EDGES;                  // self loop n -> n
        int p = atomicAdd(&g_cur[n], 1);
        g_csr[p] = n;
    }
}

// ---------------------------------------------------------------------------
// Fused GATv2 softmax + aggregation, ONE WARP PER NODE (8 nodes / 256-thr blk).
// Lane l owns channels [16l, 16l+16) (within head l/8; 8 lanes per head), so
// the head-score reduction is 3 shfls within an aligned 8-lane group. x_l/x_r
// gathered as fp16 (2x LDG.128 per lane per edge), all math in fp32.
// Softmax shift dropped (scores bounded; exp can't overflow in fp32).
__device__ __forceinline__ void unpack8(float* f, uint4 q) {
    float2 t;
    t = __half22float2(*(__half2*)&q.x); f[0] = t.x; f[1] = t.y;
    t = __half22float2(*(__half2*)&q.y); f[2] = t.x; f[3] = t.y;
    t = __half22float2(*(__half2*)&q.z); f[4] = t.x; f[5] = t.y;
    t = __half22float2(*(__half2*)&q.w); f[6] = t.x; f[7] = t.y;
}

__global__ void __launch_bounds__(256) k_aggregate(const float* __restrict__ att,
                                                   const float* __restrict__ bias,
                                                   float* __restrict__ out) {
    int w    = threadIdx.x >> 5;
    int lane = threadIdx.x & 31;
    int node = blockIdx.x * 8 + w;
    if (node >= N_NODES) return;

    float xr[16];
    {
        uint4 qa = g_xrh[node * ROW4 + 2 * lane];
        uint4 qb = g_xrh[node * ROW4 + 2 * lane + 1];
        unpack8(xr, qa); unpack8(xr + 8, qb);
    }
    float a[16];
#pragma unroll
    for (int j = 0; j < 16; j++) a[j] = att[lane * 16 + j];  // att flat [4][128]

    float acc[16];
#pragma unroll
    for (int j = 0; j < 16; j++) acc[j] = 0.f;
    float d = 0.f;

    int p   = g_off[node];
    int end = g_off[node + 1];

    // ---- main loop: 2 edges per iter, 4 LDG.128 in flight per lane ----
    for (; p + 2 <= end; p += 2) {
        int s0 = g_csr[p];
        int s1 = g_csr[p + 1];
        uint4 q0a = g_xlh[s0 * ROW4 + 2 * lane];
        uint4 q0b = g_xlh[s0 * ROW4 + 2 * lane + 1];
        uint4 q1a = g_xlh[s1 * ROW4 + 2 * lane];
        uint4 q1b = g_xlh[s1 * ROW4 + 2 * lane + 1];
        float x0[16], x1[16];
        unpack8(x0, q0a); unpack8(x0 + 8, q0b);
        unpack8(x1, q1a); unpack8(x1 + 8, q1b);

        float sc0 = 0.f, sc1 = 0.f;
#pragma unroll
        for (int j = 0; j < 16; j++) {
            float v0 = x0[j] + xr[j]; v0 = fmaxf(v0, 0.2f * v0);  // leaky relu
            sc0 = fmaf(a[j], v0, sc0);
            float v1 = x1[j] + xr[j]; v1 = fmaxf(v1, 0.2f * v1);
            sc1 = fmaf(a[j], v1, sc1);
        }
#pragma unroll
        for (int m = 4; m >= 1; m >>= 1) {
            sc0 += __shfl_xor_sync(0xffffffffu, sc0, m);
            sc1 += __shfl_xor_sync(0xffffffffu, sc1, m);
        }
        float e0 = __expf(sc0);
        float e1 = __expf(sc1);
        d += e0 + e1;
#pragma unroll
        for (int j = 0; j < 16; j++) {
            acc[j] = fmaf(e0, x0[j], acc[j]);
            acc[j] = fmaf(e1, x1[j], acc[j]);
        }
    }

    // ---- remainder (self loop guarantees end > off) ----
    for (; p < end; p++) {
        int s = g_csr[p];
        uint4 qa = g_xlh[s * ROW4 + 2 * lane];
        uint4 qb = g_xlh[s * ROW4 + 2 * lane + 1];
        float x0[16];
        unpack8(x0, qa); unpack8(x0 + 8, qb);
        float sc = 0.f;
#pragma unroll
        for (int j = 0; j < 16; j++) {
            float v = x0[j] + xr[j]; v = fmaxf(v, 0.2f * v);
            sc = fmaf(a[j], v, sc);
        }
#pragma unroll
        for (int m = 4; m >= 1; m >>= 1)
            sc += __shfl_xor_sync(0xffffffffu, sc, m);
        float e = __expf(sc);
        d += e;
#pragma unroll
        for (int j = 0; j < 16; j++) acc[j] = fmaf(e, x0[j], acc[j]);
    }

    float inv = 1.0f / d;
    float4* out4 = (float4*)out;
    const float4* b4 = (const float4*)bias;
#pragma unroll
    for (int q = 0; q < 4; q++) {
        float4 b = b4[lane * 4 + q];
        float4 o;
        o.x = fmaf(acc[q * 4 + 0], inv, b.x);
        o.y = fmaf(acc[q * 4 + 1], inv, b.y);
        o.z = fmaf(acc[q * 4 + 2], inv, b.z);
        o.w = fmaf(acc[q * 4 + 3], inv, b.w);
        out4[node * 128 + lane * 4 + q] = o;
    }
}

// ---------------------------------------------------------------------------
extern "C" void kernel_launch(void* const* d_in, const int* in_sizes, int n_in,
                              void* d_out, int out_size) {
    const float* X    = (const float*)d_in[0];       // [50000,16]
    const void*  ei   = d_in[1];                     // [2,800000] int32 or int64
    const float* Wl   = (const float*)d_in[2];       // [16,512]
    const float* Wr   = (const float*)d_in[3];       // [16,512]
    const float* att  = (const float*)d_in[4];       // [4,128]
    const float* bias = (const float*)d_in[5];       // [512]
    float*       out  = (float*)d_out;               // [50000,512]

    k_zero<<<(N_NODES + 255) / 256, 256>>>();
    k_detect<<<(N_EDGES + 255) / 256, 256>>>((const long long*)ei);
    k_convert_count<<<(N_EDGES + 255) / 256, 256>>>(ei);
    k_transform<<<(N_NODES + NODES_PER_BLOCK - 1) / NODES_PER_BLOCK, 256>>>(X, Wl, Wr);
    k_scan<<<1, 1024>>>();
    k_scatter<<<(TOTAL_EDGES + 255) / 256, 256>>>();
    k_aggregate<<<(N_NODES + 7) / 8, 256>>>(att, bias, out);
}

// round 13
// speedup vs baseline: 1.1184x; 1.1184x over previous
#include <cuda_runtime.h>
#include <cuda_fp16.h>
#include <cstdint>

#define N_NODES 50000
#define N_EDGES 800000
#define TOTAL_EDGES (N_EDGES + N_NODES)   // + self loops
#define HC  512                           // HEADS * OUT_CH
#define HC2 256                           // half2s per node row
#define ROWU2 128                         // uint2s (4 ch fp16) per node row  [FIXED: was 256]

// ---- scratch (device globals: allocation-free) ----
__device__ uint2 g_xlh[N_NODES * ROWU2];  // 51.2 MB, x_l rows fp16
__device__ uint2 g_xrh[N_NODES * ROWU2];  // 51.2 MB, x_r rows fp16
__device__ int   g_count[N_NODES];
__device__ int   g_off[N_NODES + 1];
__device__ int   g_cur[N_NODES];
__device__ int   g_csr[TOTAL_EDGES];      // src per dst-grouped slot
__device__ int   g_src[N_EDGES];
__device__ int   g_dst[N_EDGES];
__device__ int   g_not64;                 // 1 if edge_index is int32, 0 if int64

// ---------------------------------------------------------------------------
__global__ void k_zero() {
    int i = blockIdx.x * blockDim.x + threadIdx.x;
    if (i < N_NODES) g_count[i] = 0;
    if (i == 0) g_not64 = 0;
}

// Probe dtype of edge_index. Reads only the first N_EDGES int64 words (6.4 MB),
// in-bounds under either dtype. True int64 values are all in [0, N_NODES);
// misread int32 pairs have nonzero high words almost surely -> flag.
__global__ void k_detect(const long long* __restrict__ ei64) {
    int e = blockIdx.x * blockDim.x + threadIdx.x;
    if (e < N_EDGES) {
        long long v = ei64[e];
        if (v < 0 || v >= N_NODES) g_not64 = 1;   // benign race, all write 1
    }
}

// Convert to int32 src/dst AND build the degree histogram in one pass.
__global__ void k_convert_count(const void* __restrict__ ei_raw) {
    int e = blockIdx.x * blockDim.x + threadIdx.x;
    if (e >= N_EDGES) return;
    int s, d;
    if (g_not64) {
        const int* ei32 = (const int*)ei_raw;
        s = ei32[e];
        d = ei32[N_EDGES + e];
    } else {
        const long long* ei64 = (const long long*)ei_raw;
        s = (int)ei64[e];
        d = (int)ei64[N_EDGES + e];
    }
    g_src[e] = s;
    g_dst[e] = d;
    atomicAdd(&g_count[d], 1);
}

// ---------------------------------------------------------------------------
// x_l = X @ W_l, x_r = X @ W_r, both stored fp16.
// Register-resident W: 256 threads/block, thread c owns channels {2c, 2c+1}.
// Packed fma.rn.f32x2 halves FMA issue count; X staged via smem.
// Row layout: 256 __half2 per node == 128 uint2 per node (ROWU2).
#define NODES_PER_BLOCK 64
#define XBATCH 32

__global__ void __launch_bounds__(256) k_transform(const float* __restrict__ X,
                                                   const float* __restrict__ Wl,
                                                   const float* __restrict__ Wr) {
    int c   = threadIdx.x;                 // channel pair 0..255
    int nb0 = blockIdx.x * NODES_PER_BLOCK;

    unsigned long long wl[16], wr[16];
    const unsigned long long* wl2 = (const unsigned long long*)Wl;  // [16][256] f32x2
    const unsigned long long* wr2 = (const unsigned long long*)Wr;
#pragma unroll
    for (int k = 0; k < 16; k++) {
        wl[k] = wl2[k * HC2 + c];
        wr[k] = wr2[k * HC2 + c];
    }

    __shared__ float xs[XBATCH][16];
    __half2* xlh = (__half2*)g_xlh;
    __half2* xrh = (__half2*)g_xrh;

    for (int base = nb0; base < nb0 + NODES_PER_BLOCK; base += XBATCH) {
        __syncthreads();
        {
            int i0 = c;                    // 2 X elements per thread
            int n0 = base + (i0 >> 4);
            if (n0 < N_NODES) xs[i0 >> 4][i0 & 15] = X[n0 * 16 + (i0 & 15)];
            int i1 = c + 256;
            int n1 = base + (i1 >> 4);
            if (n1 < N_NODES) xs[i1 >> 4][i1 & 15] = X[n1 * 16 + (i1 & 15)];
        }
        __syncthreads();

        for (int i = 0; i < XBATCH; i++) {
            int node = base + i;
            if (node >= N_NODES) break;
            unsigned long long al, ar;
            {
                float xv = xs[i][0];
                unsigned long long xp;
                asm("mov.b64 %0, {%1, %1};" : "=l"(xp) : "f"(xv));
                asm("mul.rn.f32x2 %0, %1, %2;" : "=l"(al) : "l"(xp), "l"(wl[0]));
                asm("mul.rn.f32x2 %0, %1, %2;" : "=l"(ar) : "l"(xp), "l"(wr[0]));
            }
#pragma unroll
            for (int k = 1; k < 16; k++) {
                float xv = xs[i][k];
                unsigned long long xp;
                asm("mov.b64 %0, {%1, %1};" : "=l"(xp) : "f"(xv));
                asm("fma.rn.f32x2 %0, %1, %2, %3;" : "=l"(al) : "l"(xp), "l"(wl[k]), "l"(al));
                asm("fma.rn.f32x2 %0, %1, %2, %3;" : "=l"(ar) : "l"(xp), "l"(wr[k]), "l"(ar));
            }
            float llo, lhi, rlo, rhi;
            asm("mov.b64 {%0, %1}, %2;" : "=f"(llo), "=f"(lhi) : "l"(al));
            asm("mov.b64 {%0, %1}, %2;" : "=f"(rlo), "=f"(rhi) : "l"(ar));
            xlh[(size_t)node * HC2 + c] = __floats2half2_rn(llo, lhi);
            xrh[(size_t)node * HC2 + c] = __floats2half2_rn(rlo, rhi);
        }
    }
}

// Single-block exclusive scan over per-node degrees (+1 for self loop).
__global__ void k_scan() {
    __shared__ int sm[1024];
    int t = threadIdx.x;
    const int IT = (N_NODES + 1023) / 1024;   // 49
    int beg = t * IT;
    int end = beg + IT; if (end > N_NODES) end = N_NODES;
    int s = 0;
    for (int i = beg; i < end; i++) s += g_count[i] + 1;
    sm[t] = s;
    __syncthreads();
    for (int off = 1; off < 1024; off <<= 1) {
        int v = 0;
        if (t >= off) v = sm[t - off];
        __syncthreads();
        sm[t] += v;
        __syncthreads();
    }
    int run = sm[t] - s;                      // exclusive prefix for this chunk
    for (int i = beg; i < end; i++) {
        g_off[i] = run;
        g_cur[i] = run;
        run += g_count[i] + 1;
    }
    if (t == 1023) g_off[N_NODES] = sm[1023];
}

__global__ void k_scatter() {
    int e = blockIdx.x * blockDim.x + threadIdx.x;
    if (e < N_EDGES) {
        int p = atomicAdd(&g_cur[g_dst[e]], 1);
        g_csr[p] = g_src[e];
    } else if (e < TOTAL_EDGES) {
        int n = e - N_EDGES;                  // self loop n -> n
        int p = atomicAdd(&g_cur[n], 1);
        g_csr[p] = n;
    }
}

// ---------------------------------------------------------------------------
// Fused GATv2 score + softmax + aggregation. One block (128 thr) per dst node,
// thread t owns channels [4t, 4t+4) (one uint2 of fp16), warp w == head w.
// Edge loop: unroll-4, SOFTWARE PIPELINED one quad ahead: next quad's index
// loads + gathers are in flight while current quad is scored/accumulated.
// Softmax shift dropped (scores bounded; exp can't overflow in fp32):
// exp(s)/sum exp(s) == max-shifted reference.
__device__ __forceinline__ float4 un16(uint2 r) {
    float2 f01 = __half22float2(*(__half2*)&r.x);
    float2 f23 = __half22float2(*(__half2*)&r.y);
    return make_float4(f01.x, f01.y, f23.x, f23.y);
}

__device__ __forceinline__ float edge_score(float4 cx, float4 xr, float4 a) {
    float vx = cx.x + xr.x; vx = fmaxf(vx, 0.2f * vx);
    float vy = cx.y + xr.y; vy = fmaxf(vy, 0.2f * vy);
    float vz = cx.z + xr.z; vz = fmaxf(vz, 0.2f * vz);
    float vw = cx.w + xr.w; vw = fmaxf(vw, 0.2f * vw);
    float s = a.x * vx;
    s = fmaf(a.y, vy, s);
    s = fmaf(a.z, vz, s);
    s = fmaf(a.w, vw, s);
    return s;
}

struct Acc { float4 acc; float d; };

__device__ __forceinline__ void do_quad(uint2 r0, uint2 r1, uint2 r2, uint2 r3,
                                        float4 xr, float4 a, Acc& A) {
    float4 c0 = un16(r0);
    float4 c1 = un16(r1);
    float4 c2 = un16(r2);
    float4 c3 = un16(r3);
    float sc0 = edge_score(c0, xr, a);
    float sc1 = edge_score(c1, xr, a);
    float sc2 = edge_score(c2, xr, a);
    float sc3 = edge_score(c3, xr, a);
#pragma unroll
    for (int m = 16; m >= 1; m >>= 1) {
        sc0 += __shfl_xor_sync(0xffffffffu, sc0, m);
        sc1 += __shfl_xor_sync(0xffffffffu, sc1, m);
        sc2 += __shfl_xor_sync(0xffffffffu, sc2, m);
        sc3 += __shfl_xor_sync(0xffffffffu, sc3, m);
    }
    float e0 = __expf(sc0);
    float e1 = __expf(sc1);
    float e2 = __expf(sc2);
    float e3 = __expf(sc3);
    A.d += (e0 + e1) + (e2 + e3);
    A.acc.x = fmaf(e0, c0.x, A.acc.x); A.acc.y = fmaf(e0, c0.y, A.acc.y);
    A.acc.z = fmaf(e0, c0.z, A.acc.z); A.acc.w = fmaf(e0, c0.w, A.acc.w);
    A.acc.x = fmaf(e1, c1.x, A.acc.x); A.acc.y = fmaf(e1, c1.y, A.acc.y);
    A.acc.z = fmaf(e1, c1.z, A.acc.z); A.acc.w = fmaf(e1, c1.w, A.acc.w);
    A.acc.x = fmaf(e2, c2.x, A.acc.x); A.acc.y = fmaf(e2, c2.y, A.acc.y);
    A.acc.z = fmaf(e2, c2.z, A.acc.z); A.acc.w = fmaf(e2, c2.w, A.acc.w);
    A.acc.x = fmaf(e3, c3.x, A.acc.x); A.acc.y = fmaf(e3, c3.y, A.acc.y);
    A.acc.z = fmaf(e3, c3.z, A.acc.z); A.acc.w = fmaf(e3, c3.w, A.acc.w);
}

__global__ void __launch_bounds__(128) k_aggregate(const float* __restrict__ att,
                                                   const float* __restrict__ bias,
                                                   float* __restrict__ out) {
    int node = blockIdx.x;
    int t    = threadIdx.x;

    float4 xr = un16(g_xrh[node * ROWU2 + t]);
    float4 a  = ((const float4*)att)[t];    // att flat [h*128+c] == channels [4t..4t+3]

    Acc A;
    A.acc = make_float4(0.f, 0.f, 0.f, 0.f);
    A.d   = 0.f;

    int p   = g_off[node];
    int end = g_off[node + 1];

    // ---- pipelined quad loop: current quad in regs, next quad in flight ----
    if (p + 4 <= end) {
        uint2 q0, q1, q2, q3;
        {
            int s0 = g_csr[p + 0];
            int s1 = g_csr[p + 1];
            int s2 = g_csr[p + 2];
            int s3 = g_csr[p + 3];
            q0 = g_xlh[s0 * ROWU2 + t];
            q1 = g_xlh[s1 * ROWU2 + t];
            q2 = g_xlh[s2 * ROWU2 + t];
            q3 = g_xlh[s3 * ROWU2 + t];
        }
        p += 4;
        for (; p + 4 <= end; p += 4) {
            int s0 = g_csr[p + 0];
            int s1 = g_csr[p + 1];
            int s2 = g_csr[p + 2];
            int s3 = g_csr[p + 3];
            uint2 n0 = g_xlh[s0 * ROWU2 + t];
            uint2 n1 = g_xlh[s1 * ROWU2 + t];
            uint2 n2 = g_xlh[s2 * ROWU2 + t];
            uint2 n3 = g_xlh[s3 * ROWU2 + t];
            do_quad(q0, q1, q2, q3, xr, a, A);   // gathers above stay in flight
            q0 = n0; q1 = n1; q2 = n2; q3 = n3;
        }
        do_quad(q0, q1, q2, q3, xr, a, A);
    }

    // ---- remainder (0..3 edges; self loop guarantees end > off) ----
    for (; p < end; p++) {
        int s = g_csr[p];
        float4 cx = un16(g_xlh[s * ROWU2 + t]);
        float sc = edge_score(cx, xr, a);
#pragma unroll
        for (int m = 16; m >= 1; m >>= 1)
            sc += __shfl_xor_sync(0xffffffffu, sc, m);
        float e = __expf(sc);
        A.d += e;
        A.acc.x = fmaf(e, cx.x, A.acc.x);
        A.acc.y = fmaf(e, cx.y, A.acc.y);
        A.acc.z = fmaf(e, cx.z, A.acc.z);
        A.acc.w = fmaf(e, cx.w, A.acc.w);
    }

    float inv = 1.0f / A.d;
    float4 b = ((const float4*)bias)[t];
    float4 o;
    o.x = fmaf(A.acc.x, inv, b.x);
    o.y = fmaf(A.acc.y, inv, b.y);
    o.z = fmaf(A.acc.z, inv, b.z);
    o.w = fmaf(A.acc.w, inv, b.w);
    ((float4*)out)[node * 128 + t] = o;
}

// ---------------------------------------------------------------------------
extern "C" void kernel_launch(void* const* d_in, const int* in_sizes, int n_in,
                              void* d_out, int out_size) {
    const float* X    = (const float*)d_in[0];       // [50000,16]
    const void*  ei   = d_in[1];                     // [2,800000] int32 or int64
    const float* Wl   = (const float*)d_in[2];       // [16,512]
    const float* Wr   = (const float*)d_in[3];       // [16,512]
    const float* att  = (const float*)d_in[4];       // [4,128]
    const float* bias = (const float*)d_in[5];       // [512]
    float*       out  = (float*)d_out;               // [50000,512]

    k_zero<<<(N_NODES + 255) / 256, 256>>>();
    k_detect<<<(N_EDGES + 255) / 256, 256>>>((const long long*)ei);
    k_convert_count<<<(N_EDGES + 255) / 256, 256>>>(ei);
    k_transform<<<(N_NODES + NODES_PER_BLOCK - 1) / NODES_PER_BLOCK, 256>>>(X, Wl, Wr);
    k_scan<<<1, 1024>>>();
    k_scatter<<<(TOTAL_EDGES + 255) / 256, 256>>>();
    k_aggregate<<<N_NODES, 128>>>(att, bias, out);
}

// round 16
// speedup vs baseline: 1.2233x; 1.0937x over previous
#include <cuda_runtime.h>
#include <cuda_fp16.h>
#include <cstdint>

#define N_NODES 50000
#define N_EDGES 800000
#define TOTAL_EDGES (N_EDGES + N_NODES)   // + self loops
#define HC  512                           // HEADS * OUT_CH
#define HC2 256                           // half2s per node row
#define ROWU4 64                          // uint4s (8 ch fp16) per node row

// ---- scratch (device globals: allocation-free, uint4 => 16B aligned) ----
__device__ uint4 g_xlh[N_NODES * ROWU4];  // 51.2 MB, x_l rows fp16
__device__ uint4 g_xrh[N_NODES * ROWU4];  // 51.2 MB, x_r rows fp16
__device__ int   g_count[N_NODES];
__device__ int   g_off[N_NODES + 1];
__device__ int   g_cur[N_NODES];
__device__ int   g_csr[TOTAL_EDGES];      // src per dst-grouped slot
__device__ int   g_src[N_EDGES];
__device__ int   g_dst[N_EDGES];
__device__ int   g_not64;                 // 1 if edge_index is int32, 0 if int64

// ---------------------------------------------------------------------------
__global__ void k_zero() {
    int i = blockIdx.x * blockDim.x + threadIdx.x;
    if (i < N_NODES) g_count[i] = 0;
    if (i == 0) g_not64 = 0;
}

// Probe dtype of edge_index. Reads only the first N_EDGES int64 words (6.4 MB),
// in-bounds under either dtype. True int64 values are all in [0, N_NODES);
// misread int32 pairs have nonzero high words almost surely -> flag.
__global__ void k_detect(const long long* __restrict__ ei64) {
    int e = blockIdx.x * blockDim.x + threadIdx.x;
    if (e < N_EDGES) {
        long long v = ei64[e];
        if (v < 0 || v >= N_NODES) g_not64 = 1;   // benign race, all write 1
    }
}

// Convert to int32 src/dst AND build the degree histogram in one pass.
__global__ void k_convert_count(const void* __restrict__ ei_raw) {
    int e = blockIdx.x * blockDim.x + threadIdx.x;
    if (e >= N_EDGES) return;
    int s, d;
    if (g_not64) {
        const int* ei32 = (const int*)ei_raw;
        s = ei32[e];
        d = ei32[N_EDGES + e];
    } else {
        const long long* ei64 = (const long long*)ei_raw;
        s = (int)ei64[e];
        d = (int)ei64[N_EDGES + e];
    }
    g_src[e] = s;
    g_dst[e] = d;
    atomicAdd(&g_count[d], 1);
}

// ---------------------------------------------------------------------------
// x_l = X @ W_l, x_r = X @ W_r, both stored fp16.
// Register-resident W: 256 threads/block, thread c owns channels {2c, 2c+1}.
// Packed fma.rn.f32x2; X staged via smem; 2 nodes per inner iter (4 FMA chains).
#define NODES_PER_BLOCK 64
#define XBATCH 32

__global__ void __launch_bounds__(256) k_transform(const float* __restrict__ X,
                                                   const float* __restrict__ Wl,
                                                   const float* __restrict__ Wr) {
    int c   = threadIdx.x;                 // channel pair 0..255
    int nb0 = blockIdx.x * NODES_PER_BLOCK;

    unsigned long long wl[16], wr[16];
    const unsigned long long* wl2 = (const unsigned long long*)Wl;  // [16][256] f32x2
    const unsigned long long* wr2 = (const unsigned long long*)Wr;
#pragma unroll
    for (int k = 0; k < 16; k++) {
        wl[k] = wl2[k * HC2 + c];
        wr[k] = wr2[k * HC2 + c];
    }

    __shared__ float xs[XBATCH][16];
    __half2* xlh = (__half2*)g_xlh;
    __half2* xrh = (__half2*)g_xrh;

    for (int base = nb0; base < nb0 + NODES_PER_BLOCK; base += XBATCH) {
        __syncthreads();
        {
            int i0 = c;                    // 2 X elements per thread
            int n0 = base + (i0 >> 4);
            if (n0 < N_NODES) xs[i0 >> 4][i0 & 15] = X[n0 * 16 + (i0 & 15)];
            int i1 = c + 256;
            int n1 = base + (i1 >> 4);
            if (n1 < N_NODES) xs[i1 >> 4][i1 & 15] = X[n1 * 16 + (i1 & 15)];
        }
        __syncthreads();

        for (int i = 0; i < XBATCH; i += 2) {
            int node = base + i;
            if (node >= N_NODES) break;
            unsigned long long al0, ar0, al1, ar1;
            {
                float xv0 = xs[i][0], xv1 = xs[i + 1][0];
                unsigned long long xp0, xp1;
                asm("mov.b64 %0, {%1, %1};" : "=l"(xp0) : "f"(xv0));
                asm("mov.b64 %0, {%1, %1};" : "=l"(xp1) : "f"(xv1));
                asm("mul.rn.f32x2 %0, %1, %2;" : "=l"(al0) : "l"(xp0), "l"(wl[0]));
                asm("mul.rn.f32x2 %0, %1, %2;" : "=l"(ar0) : "l"(xp0), "l"(wr[0]));
                asm("mul.rn.f32x2 %0, %1, %2;" : "=l"(al1) : "l"(xp1), "l"(wl[0]));
                asm("mul.rn.f32x2 %0, %1, %2;" : "=l"(ar1) : "l"(xp1), "l"(wr[0]));
            }
#pragma unroll
            for (int k = 1; k < 16; k++) {
                float xv0 = xs[i][k], xv1 = xs[i + 1][k];
                unsigned long long xp0, xp1;
                asm("mov.b64 %0, {%1, %1};" : "=l"(xp0) : "f"(xv0));
                asm("mov.b64 %0, {%1, %1};" : "=l"(xp1) : "f"(xv1));
                asm("fma.rn.f32x2 %0, %1, %2, %3;" : "=l"(al0) : "l"(xp0), "l"(wl[k]), "l"(al0));
                asm("fma.rn.f32x2 %0, %1, %2, %3;" : "=l"(ar0) : "l"(xp0), "l"(wr[k]), "l"(ar0));
                asm("fma.rn.f32x2 %0, %1, %2, %3;" : "=l"(al1) : "l"(xp1), "l"(wl[k]), "l"(al1));
                asm("fma.rn.f32x2 %0, %1, %2, %3;" : "=l"(ar1) : "l"(xp1), "l"(wr[k]), "l"(ar1));
            }
            float lo, hi;
            asm("mov.b64 {%0, %1}, %2;" : "=f"(lo), "=f"(hi) : "l"(al0));
            xlh[(size_t)node * HC2 + c] = __floats2half2_rn(lo, hi);
            asm("mov.b64 {%0, %1}, %2;" : "=f"(lo), "=f"(hi) : "l"(ar0));
            xrh[(size_t)node * HC2 + c] = __floats2half2_rn(lo, hi);
            asm("mov.b64 {%0, %1}, %2;" : "=f"(lo), "=f"(hi) : "l"(al1));
            xlh[(size_t)(node + 1) * HC2 + c] = __floats2half2_rn(lo, hi);
            asm("mov.b64 {%0, %1}, %2;" : "=f"(lo), "=f"(hi) : "l"(ar1));
            xrh[(size_t)(node + 1) * HC2 + c] = __floats2half2_rn(lo, hi);
        }
    }
}

// Single-block exclusive scan over per-node degrees (+1 for self loop).
__global__ void k_scan() {
    __shared__ int sm[1024];
    int t = threadIdx.x;
    const int IT = (N_NODES + 1023) / 1024;   // 49
    int beg = t * IT;
    int end = beg + IT; if (end > N_NODES) end = N_NODES;
    int s = 0;
    for (int i = beg; i < end; i++) s += g_count[i] + 1;
    sm[t] = s;
    __syncthreads();
    for (int off = 1; off < 1024; off <<= 1) {
        int v = 0;
        if (t >= off) v = sm[t - off];
        __syncthreads();
        sm[t] += v;
        __syncthreads();
    }
    int run = sm[t] - s;                      // exclusive prefix for this chunk
    for (int i = beg; i < end; i++) {
        g_off[i] = run;
        g_cur[i] = run;
        run += g_count[i] + 1;
    }
    if (t == 1023) g_off[N_NODES] = sm[1023];
}

__global__ void k_scatter() {
    int e = blockIdx.x * blockDim.x + threadIdx.x;
    if (e < N_EDGES) {
        int p = atomicAdd(&g_cur[g_dst[e]], 1);
        g_csr[p] = g_src[e];
    } else if (e < TOTAL_EDGES) {
        int n = e - N_EDGES;                  // self loop n -> n
        int p = atomicAdd(&g_cur[n], 1);
        g_csr[p] = n;
    }
}

// ---------------------------------------------------------------------------
// Fused GATv2 score + softmax + aggregation.
// TWO WARPS per node (64 threads): warp-pair w covers channels [256w, 256w+256);
// lane l owns 8 channels (one uint4 of fp16) entirely inside head (2w + l/16).
// Score reduce is over 16-lane groups. Edges processed in PAIRS with a batched
// butterfly: 1 shfl folds the two scores onto even/odd lanes, 3 shfls reduce
// both, 1 expf per lane, 1 shfl exchanges exps (5 shfls + 1 exp per 2 edges).
// Block = 128 threads = 2 nodes. Softmax shift dropped (scores bounded; exp
// can't overflow in fp32): exp(s)/sum exp(s) == max-shifted reference.
__device__ __forceinline__ void un8(float* f, uint4 q) {
    float2 t;
    t = __half22float2(*(__half2*)&q.x); f[0] = t.x; f[1] = t.y;
    t = __half22float2(*(__half2*)&q.y); f[2] = t.x; f[3] = t.y;
    t = __half22float2(*(__half2*)&q.z); f[4] = t.x; f[5] = t.y;
    t = __half22float2(*(__half2*)&q.w); f[6] = t.x; f[7] = t.y;
}

__device__ __forceinline__ float score8(const uint4& q, const float* xr,
                                        const float* a, float* x) {
    un8(x, q);
    float s = 0.f;
#pragma unroll
    for (int j = 0; j < 8; j++) {
        float v = x[j] + xr[j];
        v = fmaxf(v, 0.2f * v);               // leaky relu
        s = fmaf(a[j], v, s);
    }
    return s;
}

__global__ void __launch_bounds__(128) k_aggregate(const float* __restrict__ att,
                                                   const float* __restrict__ bias,
                                                   float* __restrict__ out) {
    int t    = threadIdx.x;
    int node = blockIdx.x * 2 + (t >> 6);     // 2 nodes per block
    int wp   = (t >> 5) & 1;                  // warp within the node pair
    int lane = t & 31;
    if (node >= N_NODES) return;

    int i4 = wp * 32 + lane;                  // uint4 index in row (channels 8*i4..)

    float xr[8], a[8];
    un8(xr, g_xrh[node * ROWU4 + i4]);
#pragma unroll
    for (int j = 0; j < 8; j++) a[j] = att[i4 * 8 + j];   // att flat [4][128]

    float acc[8];
#pragma unroll
    for (int j = 0; j < 8; j++) acc[j] = 0.f;
    float d = 0.f;

    int p   = g_off[node];
    int end = g_off[node + 1];
    bool odd = (lane & 1);

    // ---- pipelined pair loop: current edge pair in regs, next in flight ----
    if (p + 2 <= end) {
        uint4 q0 = g_xlh[g_csr[p] * ROWU4 + i4];
        uint4 q1 = g_xlh[g_csr[p + 1] * ROWU4 + i4];
        p += 2;
        for (;;) {
            bool more = (p + 2 <= end);
            uint4 n0, n1;
            if (more) {
                n0 = g_xlh[g_csr[p] * ROWU4 + i4];
                n1 = g_xlh[g_csr[p + 1] * ROWU4 + i4];
            }
            float x0[8], x1[8];
            float sc0 = score8(q0, xr, a, x0);
            float sc1 = score8(q1, xr, a, x1);
            // batched butterfly: fold both scores, reduce 16-lane group
            float keep = odd ? sc1 : sc0;
            float send = odd ? sc0 : sc1;
            float v = keep + __shfl_xor_sync(0xffffffffu, send, 1);
            v += __shfl_xor_sync(0xffffffffu, v, 2);
            v += __shfl_xor_sync(0xffffffffu, v, 4);
            v += __shfl_xor_sync(0xffffffffu, v, 8);
            float e  = __expf(v);
            float eo = __shfl_xor_sync(0xffffffffu, e, 1);
            float e0 = odd ? eo : e;
            float e1 = odd ? e : eo;
            d += e0 + e1;
#pragma unroll
            for (int j = 0; j < 8; j++) {
                acc[j] = fmaf(e0, x0[j], acc[j]);
                acc[j] = fmaf(e1, x1[j], acc[j]);
            }
            if (!more) break;
            q0 = n0; q1 = n1;
            p += 2;
        }
    }

    // ---- remainder (0..1 edges; self loop guarantees end > off) ----
    for (; p < end; p++) {
        uint4 q = g_xlh[g_csr[p] * ROWU4 + i4];
        float x0[8];
        float sc = score8(q, xr, a, x0);
        sc += __shfl_xor_sync(0xffffffffu, sc, 1);
        sc += __shfl_xor_sync(0xffffffffu, sc, 2);
        sc += __shfl_xor_sync(0xffffffffu, sc, 4);
        sc += __shfl_xor_sync(0xffffffffu, sc, 8);
        float e = __expf(sc);
        d += e;
#pragma unroll
        for (int j = 0; j < 8; j++) acc[j] = fmaf(e, x0[j], acc[j]);
    }

    float inv = 1.0f / d;
    float4* out4 = (float4*)out;
    const float4* b4 = (const float4*)bias;
#pragma unroll
    for (int h = 0; h < 2; h++) {
        float4 b = b4[i4 * 2 + h];
        float4 o;
        o.x = fmaf(acc[h * 4 + 0], inv, b.x);
        o.y = fmaf(acc[h * 4 + 1], inv, b.y);
        o.z = fmaf(acc[h * 4 + 2], inv, b.z);
        o.w = fmaf(acc[h * 4 + 3], inv, b.w);
        out4[(size_t)node * 128 + i4 * 2 + h] = o;
    }
}

// ---------------------------------------------------------------------------
extern "C" void kernel_launch(void* const* d_in, const int* in_sizes, int n_in,
                              void* d_out, int out_size) {
    const float* X    = (const float*)d_in[0];       // [50000,16]
    const void*  ei   = d_in[1];                     // [2,800000] int32 or int64
    const float* Wl   = (const float*)d_in[2];       // [16,512]
    const float* Wr   = (const float*)d_in[3];       // [16,512]
    const float* att  = (const float*)d_in[4];       // [4,128]
    const float* bias = (const float*)d_in[5];       // [512]
    float*       out  = (float*)d_out;               // [50000,512]

    k_zero<<<(N_NODES + 255) / 256, 256>>>();
    k_detect<<<(N_EDGES + 255) / 256, 256>>>((const long long*)ei);
    k_convert_count<<<(N_EDGES + 255) / 256, 256>>>(ei);
    k_transform<<<(N_NODES + NODES_PER_BLOCK - 1) / NODES_PER_BLOCK, 256>>>(X, Wl, Wr);
    k_scan<<<1, 1024>>>();
    k_scatter<<<(TOTAL_EDGES + 255) / 256, 256>>>();
    k_aggregate<<<(N_NODES + 1) / 2, 128>>>(att, bias, out);
}